// round 3
// baseline (speedup 1.0000x reference)
#include <cuda_runtime.h>
#include <cuda_bf16.h>

// Problem constants (fixed shapes from setup_inputs)
#define BB 32
#define DD 32
#define HH 32
#define WW 32
#define PS 4
#define NPD 8
#define NPH 8
#define NPW 8
#define PATCHES_PER_BLOCK 8
#define NUM_BLOCKS (BB * NPD * NPH)           // 2048
#define TOTAL_PATCHES (BB * NPD * NPH * NPW)  // 16384
#define TOKENS 64
#define AIR0 102
#define AIR1 576
#define AIR2 3352
#define FP_SCALE 4294967296.0   // 2^32 fixed-point scale for deterministic atomics

// Zero-initialized at module load; last block resets them each run (graph-replay safe).
__device__ unsigned long long g_acc = 0ULL;
__device__ unsigned int g_ticket = 0u;

// One block = one (b,pd,ph) slab = 8 patches. 512 threads, 64 per patch.
// Patch p's tokens 0..31 live in warp 2p, tokens 32..63 in warp 2p+1.
__global__ __launch_bounds__(512, 4)
void patch_entropy_fused_kernel(const int* __restrict__ s, float* __restrict__ out) {
    // stride 68 ints (272 B, 16B-aligned) => conflict-free STS, int4-aligned halves
    __shared__ int sm[PATCHES_PER_BLOCK * 68];
    __shared__ int warp_nonair[16];
    __shared__ float red_ent[16];

    const int blk = blockIdx.x;
    const int b   = blk >> 6;
    const int rem = blk & 63;
    const int pd  = rem >> 3;
    const int ph  = rem & 7;
    const int base = b * (DD * HH * WW) + pd * (PS * HH * WW) + ph * (PS * WW);

    const int tid  = threadIdx.x;
    const int wid  = tid >> 5;
    const int lane = tid & 31;

    // ---- coalesced load of the 4x4x32 slab (512 int32) ----
    {
        const int d = tid >> 7;
        const int h = (tid >> 5) & 3;
        const int w = tid & 31;
        const int v = s[base + d * (HH * WW) + h * WW + w];
        const int p = w >> 2;
        const int t = d * 16 + h * 4 + (w & 3);
        sm[p * 68 + t] = v;   // bank = 4*p + (w&3): conflict-free
    }
    __syncthreads();

    const int pp = tid >> 6;   // patch 0..7 (uniform within each warp)
    const int tt = tid & 63;   // token 0..63; tt>=32 <=> odd warp

    const int v = sm[pp * 68 + tt];
    const bool is_air = (v == AIR0) | (v == AIR1) | (v == AIR2);

    // non-air count per warp via ballot; combine the patch's two warps via smem
    const unsigned nonair_mask = __ballot_sync(0xFFFFFFFFu, !is_air);
    if (lane == 0) warp_nonair[wid] = __popc(nonair_mask);

    // ---- occurrence count ----
    // within this warp's 32 tokens: single MATCH.ANY
    int c = __popc(__match_any_sync(0xFFFFFFFFu, v));
    // against the other half's 32 tokens: 8x LDS.128 broadcast + 32 compares
    {
        const int other_off = (wid & 1) ? 0 : 32;      // odd warp reads low half
        const int4* pb = reinterpret_cast<const int4*>(&sm[pp * 68 + other_off]);
        #pragma unroll
        for (int k = 0; k < 8; ++k) {
            const int4 u = pb[k];
            c += (u.x == v) + (u.y == v) + (u.z == v) + (u.w == v);
        }
    }

    __syncthreads();
    const int tot = warp_nonair[2 * pp] + warp_nonair[2 * pp + 1];

    // Each of the c occurrences contributes (-p*log(p+eps))/c = -(1/tot)*log(p+eps).
    float term = 0.0f;
    if (!is_air) {
        const float inv_tot = __fdividef(1.0f, (float)tot);  // tot>=1 when any non-air
        const float p = (float)c * inv_tot;
        term = -inv_tot * __logf(p + 1e-10f);
    }

    // ---- warp reduce -> smem -> warp0 block reduce -> one atomic per block ----
    #pragma unroll
    for (int off = 16; off > 0; off >>= 1)
        term += __shfl_xor_sync(0xFFFFFFFFu, term, off);
    if (lane == 0) red_ent[wid] = term;
    __syncthreads();

    if (wid == 0) {
        float x = (lane < 16) ? red_ent[lane] : 0.0f;
        #pragma unroll
        for (int off = 8; off > 0; off >>= 1)
            x += __shfl_xor_sync(0xFFFFFFFFu, x, off);
        if (lane == 0) {
            // fixed-point accumulate: integer atomics are order-invariant => deterministic
            const unsigned long long q =
                (unsigned long long)(long long)((double)x * FP_SCALE);
            atomicAdd(&g_acc, q);
            __threadfence();
            const unsigned int old = atomicAdd(&g_ticket, 1u);
            if (old == NUM_BLOCKS - 1) {
                const unsigned long long a = atomicAdd(&g_acc, 0ULL);
                const double total = (double)a / FP_SCALE;
                out[0] = (float)(total / ((double)TOTAL_PATCHES + 1e-06));
                // self-clean for the next graph replay
                g_acc = 0ULL;
                g_ticket = 0u;
            }
        }
    }
}

extern "C" void kernel_launch(void* const* d_in, const int* in_sizes, int n_in,
                              void* d_out, int out_size) {
    const int* structure = (const int*)d_in[0];
    float* out = (float*)d_out;
    patch_entropy_fused_kernel<<<NUM_BLOCKS, 512>>>(structure, out);
}

// round 4
// speedup vs baseline: 1.4650x; 1.4650x over previous
#include <cuda_runtime.h>
#include <cuda_bf16.h>

// Fixed shapes from setup_inputs: structure int32[32,32,32,32], PS=4
#define BB 32
#define DD 32
#define HH 32
#define WW 32
#define NUM_SLABS 2048                 // B * (D/4) * (H/4)
#define SLABS_PER_BLOCK 2
#define GRID_BLOCKS (NUM_SLABS / SLABS_PER_BLOCK)   // 1024
#define PATCHES_PER_BLOCK 16
#define TOTAL_PATCHES 16384
#define AIR0 102
#define AIR1 576
#define AIR2 3352
#define FP_SCALE 4294967296.0          // 2^32 fixed-point scale for deterministic atomics

// Zero-initialized at module load; last block resets them (graph-replay safe).
__device__ unsigned long long g_acc = 0ULL;
__device__ unsigned int g_ticket = 0u;

// 256 threads, 16 patches/block (two 4x4x32 slabs), 4 tokens per thread.
__global__ __launch_bounds__(256, 8)
void patch_entropy_fused_kernel(const int* __restrict__ s, float* __restrict__ out) {
    // stride 68 ints (= 17 int4) per patch: 16B-aligned, conflict-spread
    __shared__ int sm[PATCHES_PER_BLOCK * 68];
    __shared__ float logtab[65];   // log(i), log(0):=0
    __shared__ float invtab[65];   // 1/i,    1/0 :=0
    __shared__ float red_ent[8];

    const int tid = threadIdx.x;

    // ---- LUT init (65 lanes; one-time MUFUs, off the hot path) ----
    if (tid < 65) {
        const float fi = (float)tid;
        logtab[tid] = (tid == 0) ? 0.0f : __logf(fi);
        invtab[tid] = (tid == 0) ? 0.0f : __fdividef(1.0f, fi);
    }

    // ---- coalesced int4 load of two slabs (1024 int32) ----
    {
        const int slab = tid >> 7;          // 0..1
        const int idx  = tid & 127;
        const int d  = idx >> 5;            // 0..3
        const int h  = (idx >> 3) & 3;      // 0..3
        const int w4 = idx & 7;             // int4 within row => patch id
        const int gslab = blockIdx.x * SLABS_PER_BLOCK + slab;
        const int b   = gslab >> 6;
        const int rem = gslab & 63;
        const int pd  = rem >> 3;
        const int ph  = rem & 7;
        const int base = b * (DD * HH * WW) + pd * (4 * HH * WW) + ph * (4 * WW);
        const int4 val = *(const int4*)(s + base + d * (HH * WW) + h * WW + w4 * 4);
        const int p = slab * 8 + w4;
        const int t = d * 16 + h * 4;       // tokens t..t+3, int4-aligned
        *(int4*)&sm[p * 68 + t] = val;
    }
    __syncthreads();

    // ---- compute: thread owns 4 consecutive tokens of patch pp ----
    const int pp = tid >> 4;    // 0..15
    const int q  = tid & 15;    // quarter-row within patch
    const int4* pbase = (const int4*)&sm[pp * 68];

    const int4 mine = pbase[q];
    const int v0 = mine.x, v1 = mine.y, v2 = mine.z, v3 = mine.w;

    const int a0 = (v0 == AIR0) | (v0 == AIR1) | (v0 == AIR2);
    const int a1 = (v1 == AIR0) | (v1 == AIR1) | (v1 == AIR2);
    const int a2 = (v2 == AIR0) | (v2 == AIR1) | (v2 == AIR2);
    const int a3 = (v3 == AIR0) | (v3 == AIR1) | (v3 == AIR2);
    int na = (4 - a0 - a1 - a2 - a3);   // non-air among own tokens

    // occurrence counts: 16x LDS.128 broadcast, 4 tokens amortize each load
    int c0 = 0, c1 = 0, c2 = 0, c3 = 0;
    #pragma unroll
    for (int k = 0; k < 16; ++k) {
        const int4 u = pbase[k];
        c0 += (u.x == v0) + (u.y == v0) + (u.z == v0) + (u.w == v0);
        c1 += (u.x == v1) + (u.y == v1) + (u.z == v1) + (u.w == v1);
        c2 += (u.x == v2) + (u.y == v2) + (u.z == v2) + (u.w == v2);
        c3 += (u.x == v3) + (u.y == v3) + (u.z == v3) + (u.w == v3);
    }

    // tot = non-air tokens in this patch: reduce na over the 16-thread group
    int tot = na;
    #pragma unroll
    for (int off = 8; off > 0; off >>= 1)
        tot += __shfl_xor_sync(0xFFFFFFFFu, tot, off);

    // entropy contribution of this thread's tokens:
    //   sum over own non-air tokens of inv_tot * (log(tot) - log(c))
    float sl = 0.0f;
    if (!a0) sl += logtab[c0];
    if (!a1) sl += logtab[c1];
    if (!a2) sl += logtab[c2];
    if (!a3) sl += logtab[c3];
    const float term = invtab[tot] * ((float)na * logtab[tot] - sl);

    // ---- block-level sum of terms (patches already individually scaled) ----
    float x = term;
    #pragma unroll
    for (int off = 16; off > 0; off >>= 1)
        x += __shfl_xor_sync(0xFFFFFFFFu, x, off);
    const int wid = tid >> 5, lane = tid & 31;
    if (lane == 0) red_ent[wid] = x;
    __syncthreads();

    if (wid == 0) {
        float y = (lane < 8) ? red_ent[lane] : 0.0f;
        #pragma unroll
        for (int off = 4; off > 0; off >>= 1)
            y += __shfl_xor_sync(0xFFFFFFFFu, y, off);
        if (lane == 0) {
            // fixed-point accumulate: integer atomics are order-invariant => deterministic
            const unsigned long long qv =
                (unsigned long long)(long long)((double)y * FP_SCALE);
            atomicAdd(&g_acc, qv);
            __threadfence();
            const unsigned int old = atomicAdd(&g_ticket, 1u);
            if (old == GRID_BLOCKS - 1) {
                const unsigned long long a = atomicAdd(&g_acc, 0ULL);
                const double total = (double)a / FP_SCALE;
                out[0] = (float)(total / ((double)TOTAL_PATCHES + 1e-06));
                // self-clean for the next graph replay
                g_acc = 0ULL;
                g_ticket = 0u;
            }
        }
    }
}

extern "C" void kernel_launch(void* const* d_in, const int* in_sizes, int n_in,
                              void* d_out, int out_size) {
    const int* structure = (const int*)d_in[0];
    float* out = (float*)d_out;
    patch_entropy_fused_kernel<<<GRID_BLOCKS, 256>>>(structure, out);
}